// round 7
// baseline (speedup 1.0000x reference)
#include <cuda_runtime.h>
#include <cstdint>

#define B_ 1024
#define N_ 128

// int8 operand images + scales (prep writes, main reads)
// g_xq: [mtile 4][chunk 8][m 256][8 u32]; chunks 0-3 = Q1 (k32 each), 4-7 = Q2
__device__ __align__(16) unsigned g_xq[4 * 8 * 256 * 8];          // 256 KB
__device__ float g_xs[B_];                                        // 2^e/127 per row
// g_pbq: per (node i, tile t): [chunk 8][n 128][8 u32]; 0-3 = P1, 4-7 = P2
__device__ __align__(16) unsigned g_pbq[(size_t)N_ * 9 * 8192];   // 37.7 MB
__device__ float g_ws[N_ * 9 * 128];                              // 2^f/127 per col

// ---------------- helpers ----------------
__device__ __forceinline__ uint32_t smem_u32(const void* p) {
    uint32_t a;
    asm("{ .reg .u64 t; cvta.to.shared.u64 t, %1; cvt.u32.u64 %0, t; }" : "=r"(a) : "l"(p));
    return a;
}
__device__ __forceinline__ float i2f22(int s) {   // exact for |s| < 2^22
    return __int_as_float(0x4B400000 + s) - 12582912.0f;
}
__device__ __forceinline__ unsigned pk4(int a, int b, int c, int d) {
    return (unsigned)(a & 255) | ((unsigned)(b & 255) << 8) |
           ((unsigned)(c & 255) << 16) | ((unsigned)d << 24);
}
__device__ __forceinline__ void quant2(float v, float s, int& q1, int& q2) {
    float t = v * s;                 // |t| < 127
    float r1 = rintf(t);
    q1 = (int)r1;
    q2 = (int)rintf((t - r1) * 254.0f);   // |q2| <= 127
}

#define CP16(s, g) asm volatile("cp.async.cg.shared.global [%0], [%1], 16;" :: "r"(s), "l"(g))
#define CP_COMMIT() asm volatile("cp.async.commit_group;" ::: "memory")
#define CP_WAIT(n)  asm volatile("cp.async.wait_group %0;" :: "n"(n) : "memory")

#define LDM4(r0, r1, r2, r3, a) \
    asm volatile("ldmatrix.sync.aligned.m8n8.x4.shared.b16 {%0,%1,%2,%3}, [%4];" \
        : "=r"(r0), "=r"(r1), "=r"(r2), "=r"(r3) : "r"(a))

#define MMAS8(c, a, b) \
    asm volatile("mma.sync.aligned.m16n8k32.row.col.s32.s8.s8.s32 " \
        "{%0,%1,%2,%3}, {%4,%5,%6,%7}, {%8,%9}, {%0,%1,%2,%3};" \
        : "+r"((c)[0]), "+r"((c)[1]), "+r"((c)[2]), "+r"((c)[3]) \
        : "r"((a)[0]), "r"((a)[1]), "r"((a)[2]), "r"((a)[3]), "r"((b)[0]), "r"((b)[1]))

// ---------------- prep: x -> two-level int8, per-row pow2 scale ----------------
__global__ void prep_x(const float* __restrict__ x) {
    const int row = blockIdx.x * 8 + (threadIdx.x >> 5);
    const int l = threadIdx.x & 31;
    float4 v = reinterpret_cast<const float4*>(x + (size_t)row * 128)[l];
    float m = fmaxf(fmaxf(fabsf(v.x), fabsf(v.y)), fmaxf(fabsf(v.z), fabsf(v.w)));
#pragma unroll
    for (int o = 16; o; o >>= 1) m = fmaxf(m, __shfl_xor_sync(0xffffffffu, m, o));
    m = fmaxf(m, 1e-20f);
    int e = ((__float_as_int(m) >> 23) & 255) - 126;   // 2^e > m
    float s = ldexpf(127.0f, -e);
    int q1[4], q2[4];
    quant2(v.x, s, q1[0], q2[0]);
    quant2(v.y, s, q1[1], q2[1]);
    quant2(v.z, s, q1[2], q2[2]);
    quant2(v.w, s, q1[3], q2[3]);
    const int mt = row >> 8, mm = row & 255;
    g_xq[(((size_t)mt * 8 + (l >> 3)) * 256 + mm) * 8 + (l & 7)]     = pk4(q1[0], q1[1], q1[2], q1[3]);
    g_xq[(((size_t)mt * 8 + 4 + (l >> 3)) * 256 + mm) * 8 + (l & 7)] = pk4(q2[0], q2[1], q2[2], q2[3]);
    if (l == 0) g_xs[row] = ldexpf(1.0f / 127.0f, e);
}

// ---------------- prep: weights -> two-level int8, per-col pow2 scale ----------
__global__ void prep_w(const float* __restrict__ fw, const float* __restrict__ gw) {
    extern __shared__ float s[];                 // s[n*132 + k]
    const int t = blockIdx.x, i = blockIdx.y, tid = threadIdx.x;
    const float* src = (t < 8) ? (gw + (size_t)i * 131072 + t * 128)
                               : (fw + (size_t)i * 16384);
    const int stride = (t < 8) ? 1024 : 128;
    for (int idx = tid; idx < 128 * 128; idx += 256) {
        int k = idx >> 7, n = idx & 127;
        s[n * 132 + k] = src[(size_t)k * stride + n];
    }
    __syncthreads();
    const int l = tid & 31, wid = tid >> 5;
    unsigned* out = g_pbq + (size_t)(i * 9 + t) * 8192;
    for (int cc = 0; cc < 16; ++cc) {
        const int n = wid * 16 + cc;
        float4 v = reinterpret_cast<const float4*>(s + n * 132)[l];
        float m = fmaxf(fmaxf(fabsf(v.x), fabsf(v.y)), fmaxf(fabsf(v.z), fabsf(v.w)));
#pragma unroll
        for (int o = 16; o; o >>= 1) m = fmaxf(m, __shfl_xor_sync(0xffffffffu, m, o));
        m = fmaxf(m, 1e-20f);
        int e = ((__float_as_int(m) >> 23) & 255) - 126;
        float sc = ldexpf(127.0f, -e);
        int q1[4], q2[4];
        quant2(v.x, sc, q1[0], q2[0]);
        quant2(v.y, sc, q1[1], q2[1]);
        quant2(v.z, sc, q1[2], q2[2]);
        quant2(v.w, sc, q1[3], q2[3]);
        out[((l >> 3) * 128 + n) * 8 + (l & 7)]       = pk4(q1[0], q1[1], q1[2], q1[3]);
        out[((4 + (l >> 3)) * 128 + n) * 8 + (l & 7)] = pk4(q2[0], q2[1], q2[2], q2[3]);
        if (l == 0) g_ws[(i * 9 + t) * 128 + n] = ldexpf(1.0f / 127.0f, e);
    }
}

// ---------------- main fused kernel ----------------
// grid (4 m-tiles of 256 rows, 128 nodes), 256 threads (8 warps, 2/SMSP)
// smem: XA 64KB | B0 32KB | B1 32KB | Wg 512 | Wf 512 | Cs 4608
#define SM_XA 0
#define SM_B0 65536
#define SM_WG 131072
#define SM_WF 131584
#define SM_CS 132096
#define SM_TOT 136704

__global__ __launch_bounds__(256, 1)
void sde_main(const float* __restrict__ Wf, const float* __restrict__ bfv,
              const float* __restrict__ Wg, const float* __restrict__ bgv,
              float* __restrict__ fout, float* __restrict__ gout) {
    extern __shared__ char smem[];
    const uint32_t sb = smem_u32(smem);
    const int tid = threadIdx.x, l = tid & 31, wid = tid >> 5;
    const int i = blockIdx.y, b0 = blockIdx.x * 256;
    const int warp_m = (wid & 3) * 64, warp_n = (wid >> 2) * 64;
    float* Wg_s = (float*)(smem + SM_WG);
    float* Wf_s = (float*)(smem + SM_WF);
    float* Cs_s = (float*)(smem + SM_CS);

    const char* asrc = (const char*)g_xq + (size_t)blockIdx.x * 65536;
    const char* bsrc = (const char*)(g_pbq + (size_t)(i * 9) * 8192);
#pragma unroll
    for (int j = 0; j < 16; ++j) {
        uint32_t off = (uint32_t)(j * 256 + tid) * 16;
        CP16(sb + SM_XA + off, asrc + off);
    }
#pragma unroll
    for (int j = 0; j < 8; ++j) {
        uint32_t off = (uint32_t)(j * 256 + tid) * 16;
        CP16(sb + SM_B0 + off, bsrc + off);
    }
    CP_COMMIT();
    if (tid < 128) { Wg_s[tid] = Wg[i * 128 + tid]; Wf_s[tid] = Wf[i * 128 + tid]; }
    for (int j = tid; j < 1152; j += 256) Cs_s[j] = g_ws[i * 1152 + j];

    float rs[8];
#pragma unroll
    for (int slot = 0; slot < 8; ++slot)
        rs[slot] = g_xs[b0 + warp_m + (slot >> 1) * 16 + (slot & 1) * 8 + (l >> 2)];

    const uint32_t aoff = (uint32_t)((warp_m + (l & 15)) * 32 + (l >> 4) * 16);

    float accg[8][2], accf[8];
#pragma unroll
    for (int r = 0; r < 8; ++r) { accg[r][0] = 0.f; accg[r][1] = 0.f; accf[r] = 0.f; }

    for (int t = 0; t < 9; ++t) {
        if (t + 1 < 9) {
            uint32_t dst = sb + SM_B0 + ((t + 1) & 1) * 32768;
            const char* src = bsrc + (size_t)(t + 1) * 32768;
#pragma unroll
            for (int j = 0; j < 8; ++j) {
                uint32_t off = (uint32_t)(j * 256 + tid) * 16;
                CP16(dst + off, src + off);
            }
            CP_COMMIT();
            CP_WAIT(1);
        } else {
            CP_WAIT(0);
        }
        __syncthreads();
        const uint32_t bbase = sb + SM_B0 + (t & 1) * 32768;

#pragma unroll
        for (int half = 0; half < 2; ++half) {
            const uint32_t boff = bbase +
                (uint32_t)((warp_n + half * 32 + (l & 15)) * 32 + (l >> 4) * 16);
            int ac1[4][4][4], ac2[4][4][4];
#pragma unroll
            for (int in = 0; in < 4; ++in)
#pragma unroll
                for (int im = 0; im < 4; ++im)
#pragma unroll
                    for (int r = 0; r < 4; ++r) { ac1[in][im][r] = 0; ac2[in][im][r] = 0; }

#pragma unroll
            for (int s = 0; s < 4; ++s) {
                uint32_t af1[4][4], af2[4][4], b1[4][2], b2[4][2];
#pragma unroll
                for (int im = 0; im < 4; ++im) {
                    LDM4(af1[im][0], af1[im][1], af1[im][2], af1[im][3],
                         sb + SM_XA + s * 8192 + aoff + im * 512);
                    LDM4(af2[im][0], af2[im][1], af2[im][2], af2[im][3],
                         sb + SM_XA + (4 + s) * 8192 + aoff + im * 512);
                }
#pragma unroll
                for (int pr = 0; pr < 2; ++pr) {
                    LDM4(b1[2 * pr][0], b1[2 * pr + 1][0], b1[2 * pr][1], b1[2 * pr + 1][1],
                         boff + s * 4096 + pr * 512);
                    LDM4(b2[2 * pr][0], b2[2 * pr + 1][0], b2[2 * pr][1], b2[2 * pr + 1][1],
                         boff + (4 + s) * 4096 + pr * 512);
                }
#pragma unroll
                for (int im = 0; im < 4; ++im)
#pragma unroll
                    for (int in = 0; in < 4; ++in)
                        MMAS8(ac1[in][im], af1[im], b1[in]);
#pragma unroll
                for (int im = 0; im < 4; ++im)
#pragma unroll
                    for (int in = 0; in < 4; ++in)
                        MMAS8(ac2[in][im], af1[im], b2[in]);
#pragma unroll
                for (int im = 0; im < 4; ++im)
#pragma unroll
                    for (int in = 0; in < 4; ++in)
                        MMAS8(ac2[in][im], af2[im], b1[in]);
            }

            // fused epilogue for this n-half
#pragma unroll
            for (int in = 0; in < 4; ++in) {
                const int colb = half * 32 + in * 8 + 2 * (l & 3);
                const float cs0 = Cs_s[t * 128 + warp_n + colb];
                const float cs1 = Cs_s[t * 128 + warp_n + colb + 1];
                float w = 0.f, wf0 = 0.f, wf1 = 0.f;
                if (t < 8) w = Wg_s[t * 16 + (wid >> 2) * 8 + half * 4 + in];
                else { wf0 = Wf_s[warp_n + colb]; wf1 = Wf_s[warp_n + colb + 1]; }
#pragma unroll
                for (int im = 0; im < 4; ++im)
#pragma unroll
                    for (int r = 0; r < 4; ++r) {
                        const int slot = im * 2 + (r >> 1);
                        float S1 = i2f22(ac1[in][im][r]);
                        float S2 = i2f22(ac2[in][im][r]);
                        float v = fmaf(S2, (1.0f / 254.0f), S1) * rs[slot] *
                                  ((r & 1) ? cs1 : cs0);
                        float ev = v > 0.0f ? v : (__expf(v) - 1.0f);
                        if (t < 8) accg[slot][r & 1] = fmaf(w, ev, accg[slot][r & 1]);
                        else       accf[slot] = fmaf((r & 1) ? wf1 : wf0, ev, accf[slot]);
                    }
            }
        }
        __syncthreads();
    }

    // cross-warp reduction: warps 4-7 (n 64-127) hand partials to warps 0-3
    float* red = (float*)smem;                  // reuse XA region
    const int rbase = ((wid & 3) * 32 + l) * 24;
    if (wid >= 4) {
#pragma unroll
        for (int r = 0; r < 8; ++r) {
            red[rbase + 2 * r]     = accg[r][0];
            red[rbase + 2 * r + 1] = accg[r][1];
            red[rbase + 16 + r]    = accf[r];
        }
    }
    __syncthreads();
    if (wid < 4) {
        const float bgi = bgv[i], bfi = bfv[i];
#pragma unroll
        for (int r = 0; r < 8; ++r) {
            float g0 = accg[r][0] + red[rbase + 2 * r];
            float g1 = accg[r][1] + red[rbase + 2 * r + 1];
            float vf = accf[r] + red[rbase + 16 + r];
            const int row = b0 + warp_m + (r >> 1) * 16 + (r & 1) * 8 + (l >> 2);
            *reinterpret_cast<float2*>(gout + ((size_t)row * 128 + i) * 8 + 2 * (l & 3)) =
                make_float2(g0 + bgi, g1 + bgi);
            vf += __shfl_xor_sync(0xffffffffu, vf, 1);
            vf += __shfl_xor_sync(0xffffffffu, vf, 2);
            if ((l & 3) == 0) fout[(size_t)row * 128 + i] = vf + bfi;
        }
    }
}

// ---------------- launch ----------------
extern "C" void kernel_launch(void* const* d_in, const int* in_sizes, int n_in,
                              void* d_out, int out_size) {
    (void)in_sizes; (void)n_in; (void)out_size;
    const float* x  = (const float*)d_in[0];
    const float* fw = (const float*)d_in[1];
    const float* gw = (const float*)d_in[2];
    const float* Wf = (const float*)d_in[3];
    const float* bf = (const float*)d_in[4];
    const float* Wg = (const float*)d_in[5];
    const float* bg = (const float*)d_in[6];
    float* out  = (float*)d_out;
    float* fout = out;                      // [B,N]
    float* gout = out + (size_t)B_ * N_;    // [B,N,D]

    static bool attr_set = false;
    if (!attr_set) {
        cudaFuncSetAttribute(prep_w, cudaFuncAttributeMaxDynamicSharedMemorySize, 128 * 132 * 4);
        cudaFuncSetAttribute(sde_main, cudaFuncAttributeMaxDynamicSharedMemorySize, SM_TOT);
        attr_set = true;
    }

    prep_x<<<128, 256>>>(x);
    prep_w<<<dim3(9, 128), 256, 128 * 132 * 4>>>(fw, gw);
    sde_main<<<dim3(4, 128), 256, SM_TOT>>>(Wf, bf, Wg, bg, fout, gout);
}

// round 8
// speedup vs baseline: 1.0012x; 1.0012x over previous
#include <cuda_runtime.h>
#include <cstdint>

#define B_ 1024
#define N_ 128

// int8 operand images + scales (prep writes, main reads)
// g_xq: [mtile 4][chunk 8][m 256][8 u32]; chunks 0-3 = Q1 (k32 each), 4-7 = Q2
__device__ __align__(16) unsigned g_xq[4 * 8 * 256 * 8];          // 256 KB
__device__ float g_xs[B_];                                        // 2^e/127 per row
// g_pbq: per (node i, tile t): [chunk 8][n 128][8 u32]; 0-3 = P1, 4-7 = P2
__device__ __align__(16) unsigned g_pbq[(size_t)N_ * 9 * 8192];   // 37.7 MB
__device__ float g_ws[N_ * 9 * 128];                              // 2^f/127 per col

// ---------------- helpers ----------------
__device__ __forceinline__ uint32_t smem_u32(const void* p) {
    uint32_t a;
    asm("{ .reg .u64 t; cvta.to.shared.u64 t, %1; cvt.u32.u64 %0, t; }" : "=r"(a) : "l"(p));
    return a;
}
__device__ __forceinline__ float i2f22(int s) {   // exact for |s| < 2^22
    return __int_as_float(0x4B400000 + s) - 12582912.0f;
}
__device__ __forceinline__ unsigned pk4(int a, int b, int c, int d) {
    return (unsigned)(a & 255) | ((unsigned)(b & 255) << 8) |
           ((unsigned)(c & 255) << 16) | ((unsigned)d << 24);
}
__device__ __forceinline__ void quant2(float v, float s, int& q1, int& q2) {
    float t = v * s;                 // |t| < 127
    float r1 = rintf(t);
    q1 = (int)r1;
    q2 = (int)rintf((t - r1) * 254.0f);   // |q2| <= 127
}

#define CP16(s, g) asm volatile("cp.async.cg.shared.global [%0], [%1], 16;" :: "r"(s), "l"(g))
#define CP_COMMIT() asm volatile("cp.async.commit_group;" ::: "memory")
#define CP_WAIT(n)  asm volatile("cp.async.wait_group %0;" :: "n"(n) : "memory")

#define LDM4(r0, r1, r2, r3, a) \
    asm volatile("ldmatrix.sync.aligned.m8n8.x4.shared.b16 {%0,%1,%2,%3}, [%4];" \
        : "=r"(r0), "=r"(r1), "=r"(r2), "=r"(r3) : "r"(a))

#define MMAS8(c, a, b) \
    asm volatile("mma.sync.aligned.m16n8k32.row.col.s32.s8.s8.s32 " \
        "{%0,%1,%2,%3}, {%4,%5,%6,%7}, {%8,%9}, {%0,%1,%2,%3};" \
        : "+r"((c)[0]), "+r"((c)[1]), "+r"((c)[2]), "+r"((c)[3]) \
        : "r"((a)[0]), "r"((a)[1]), "r"((a)[2]), "r"((a)[3]), "r"((b)[0]), "r"((b)[1]))

// ---------------- prep: x -> two-level int8, per-row pow2 scale ----------------
__global__ void prep_x(const float* __restrict__ x) {
    const int row = blockIdx.x * 8 + (threadIdx.x >> 5);
    const int l = threadIdx.x & 31;
    float4 v = reinterpret_cast<const float4*>(x + (size_t)row * 128)[l];
    float m = fmaxf(fmaxf(fabsf(v.x), fabsf(v.y)), fmaxf(fabsf(v.z), fabsf(v.w)));
#pragma unroll
    for (int o = 16; o; o >>= 1) m = fmaxf(m, __shfl_xor_sync(0xffffffffu, m, o));
    m = fmaxf(m, 1e-20f);
    int e = ((__float_as_int(m) >> 23) & 255) - 126;   // 2^e > m
    float s = ldexpf(127.0f, -e);
    int q1[4], q2[4];
    quant2(v.x, s, q1[0], q2[0]);
    quant2(v.y, s, q1[1], q2[1]);
    quant2(v.z, s, q1[2], q2[2]);
    quant2(v.w, s, q1[3], q2[3]);
    const int mt = row >> 8, mm = row & 255;
    g_xq[(((size_t)mt * 8 + (l >> 3)) * 256 + mm) * 8 + (l & 7)]     = pk4(q1[0], q1[1], q1[2], q1[3]);
    g_xq[(((size_t)mt * 8 + 4 + (l >> 3)) * 256 + mm) * 8 + (l & 7)] = pk4(q2[0], q2[1], q2[2], q2[3]);
    if (l == 0) g_xs[row] = ldexpf(1.0f / 127.0f, e);
}

// ---------------- prep: weights -> two-level int8, per-col pow2 scale ----------
__global__ void prep_w(const float* __restrict__ fw, const float* __restrict__ gw) {
    extern __shared__ float s[];                 // s[n*132 + k]
    const int t = blockIdx.x, i = blockIdx.y, tid = threadIdx.x;
    const float* src = (t < 8) ? (gw + (size_t)i * 131072 + t * 128)
                               : (fw + (size_t)i * 16384);
    const int stride = (t < 8) ? 1024 : 128;
    for (int idx = tid; idx < 128 * 128; idx += 256) {
        int k = idx >> 7, n = idx & 127;
        s[n * 132 + k] = src[(size_t)k * stride + n];
    }
    __syncthreads();
    const int l = tid & 31, wid = tid >> 5;
    unsigned* out = g_pbq + (size_t)(i * 9 + t) * 8192;
    for (int cc = 0; cc < 16; ++cc) {
        const int n = wid * 16 + cc;
        float4 v = reinterpret_cast<const float4*>(s + n * 132)[l];
        float m = fmaxf(fmaxf(fabsf(v.x), fabsf(v.y)), fmaxf(fabsf(v.z), fabsf(v.w)));
#pragma unroll
        for (int o = 16; o; o >>= 1) m = fmaxf(m, __shfl_xor_sync(0xffffffffu, m, o));
        m = fmaxf(m, 1e-20f);
        int e = ((__float_as_int(m) >> 23) & 255) - 126;
        float sc = ldexpf(127.0f, -e);
        int q1[4], q2[4];
        quant2(v.x, sc, q1[0], q2[0]);
        quant2(v.y, sc, q1[1], q2[1]);
        quant2(v.z, sc, q1[2], q2[2]);
        quant2(v.w, sc, q1[3], q2[3]);
        out[((l >> 3) * 128 + n) * 8 + (l & 7)]       = pk4(q1[0], q1[1], q1[2], q1[3]);
        out[((4 + (l >> 3)) * 128 + n) * 8 + (l & 7)] = pk4(q2[0], q2[1], q2[2], q2[3]);
        if (l == 0) g_ws[(i * 9 + t) * 128 + n] = ldexpf(1.0f / 127.0f, e);
    }
}

// ---------------- main fused kernel ----------------
// grid (4 m-tiles of 256 rows, 128 nodes), 256 threads (8 warps, 2/SMSP)
// smem: XA 64KB | B0 32KB | B1 32KB | Wg 512 | Wf 512 | Cs 4608
#define SM_XA 0
#define SM_B0 65536
#define SM_WG 131072
#define SM_WF 131584
#define SM_CS 132096
#define SM_TOT 136704

__global__ __launch_bounds__(256, 1)
void sde_main(const float* __restrict__ Wf, const float* __restrict__ bfv,
              const float* __restrict__ Wg, const float* __restrict__ bgv,
              float* __restrict__ fout, float* __restrict__ gout) {
    extern __shared__ char smem[];
    const uint32_t sb = smem_u32(smem);
    const int tid = threadIdx.x, l = tid & 31, wid = tid >> 5;
    const int i = blockIdx.y, b0 = blockIdx.x * 256;
    const int warp_m = (wid & 3) * 64, warp_n = (wid >> 2) * 64;
    float* Wg_s = (float*)(smem + SM_WG);
    float* Wf_s = (float*)(smem + SM_WF);
    float* Cs_s = (float*)(smem + SM_CS);

    const char* asrc = (const char*)g_xq + (size_t)blockIdx.x * 65536;
    const char* bsrc = (const char*)(g_pbq + (size_t)(i * 9) * 8192);
#pragma unroll
    for (int j = 0; j < 16; ++j) {
        uint32_t off = (uint32_t)(j * 256 + tid) * 16;
        CP16(sb + SM_XA + off, asrc + off);
    }
#pragma unroll
    for (int j = 0; j < 8; ++j) {
        uint32_t off = (uint32_t)(j * 256 + tid) * 16;
        CP16(sb + SM_B0 + off, bsrc + off);
    }
    CP_COMMIT();
    if (tid < 128) { Wg_s[tid] = Wg[i * 128 + tid]; Wf_s[tid] = Wf[i * 128 + tid]; }
    for (int j = tid; j < 1152; j += 256) Cs_s[j] = g_ws[i * 1152 + j];

    float rs[8];
#pragma unroll
    for (int slot = 0; slot < 8; ++slot)
        rs[slot] = g_xs[b0 + warp_m + (slot >> 1) * 16 + (slot & 1) * 8 + (l >> 2)];

    const uint32_t aoff = (uint32_t)((warp_m + (l & 15)) * 32 + (l >> 4) * 16);

    float accg[8][2], accf[8];
#pragma unroll
    for (int r = 0; r < 8; ++r) { accg[r][0] = 0.f; accg[r][1] = 0.f; accf[r] = 0.f; }

    for (int t = 0; t < 9; ++t) {
        if (t + 1 < 9) {
            uint32_t dst = sb + SM_B0 + ((t + 1) & 1) * 32768;
            const char* src = bsrc + (size_t)(t + 1) * 32768;
#pragma unroll
            for (int j = 0; j < 8; ++j) {
                uint32_t off = (uint32_t)(j * 256 + tid) * 16;
                CP16(dst + off, src + off);
            }
            CP_COMMIT();
            CP_WAIT(1);
        } else {
            CP_WAIT(0);
        }
        __syncthreads();
        const uint32_t bbase = sb + SM_B0 + (t & 1) * 32768;

#pragma unroll
        for (int half = 0; half < 2; ++half) {
            const uint32_t boff = bbase +
                (uint32_t)((warp_n + half * 32 + (l & 15)) * 32 + (l >> 4) * 16);
#pragma unroll
            for (int hm = 0; hm < 2; ++hm) {          // m-half: 32 of 64 rows
                int ac1[4][2][4], ac2[4][2][4];
#pragma unroll
                for (int in = 0; in < 4; ++in)
#pragma unroll
                    for (int im = 0; im < 2; ++im)
#pragma unroll
                        for (int r = 0; r < 4; ++r) { ac1[in][im][r] = 0; ac2[in][im][r] = 0; }

#pragma unroll
                for (int s = 0; s < 4; ++s) {
                    uint32_t af1[2][4], af2[2][4], b1[4][2], b2[4][2];
#pragma unroll
                    for (int im = 0; im < 2; ++im) {
                        const uint32_t ime = (uint32_t)(hm * 2 + im) * 512;
                        LDM4(af1[im][0], af1[im][1], af1[im][2], af1[im][3],
                             sb + SM_XA + s * 8192 + aoff + ime);
                        LDM4(af2[im][0], af2[im][1], af2[im][2], af2[im][3],
                             sb + SM_XA + (4 + s) * 8192 + aoff + ime);
                    }
#pragma unroll
                    for (int pr = 0; pr < 2; ++pr) {
                        LDM4(b1[2 * pr][0], b1[2 * pr + 1][0], b1[2 * pr][1], b1[2 * pr + 1][1],
                             boff + s * 4096 + pr * 512);
                        LDM4(b2[2 * pr][0], b2[2 * pr + 1][0], b2[2 * pr][1], b2[2 * pr + 1][1],
                             boff + (4 + s) * 4096 + pr * 512);
                    }
#pragma unroll
                    for (int im = 0; im < 2; ++im)
#pragma unroll
                        for (int in = 0; in < 4; ++in)
                            MMAS8(ac1[in][im], af1[im], b1[in]);
#pragma unroll
                    for (int im = 0; im < 2; ++im)
#pragma unroll
                        for (int in = 0; in < 4; ++in)
                            MMAS8(ac2[in][im], af1[im], b2[in]);
#pragma unroll
                    for (int im = 0; im < 2; ++im)
#pragma unroll
                        for (int in = 0; in < 4; ++in)
                            MMAS8(ac2[in][im], af2[im], b1[in]);
                }

                // fused epilogue for this 32x32 sub-block
#pragma unroll
                for (int in = 0; in < 4; ++in) {
                    const int colb = half * 32 + in * 8 + 2 * (l & 3);
                    const float cs0 = Cs_s[t * 128 + warp_n + colb];
                    const float cs1 = Cs_s[t * 128 + warp_n + colb + 1];
                    float w = 0.f, wf0 = 0.f, wf1 = 0.f;
                    if (t < 8) w = Wg_s[t * 16 + (wid >> 2) * 8 + half * 4 + in];
                    else { wf0 = Wf_s[warp_n + colb]; wf1 = Wf_s[warp_n + colb + 1]; }
#pragma unroll
                    for (int im = 0; im < 2; ++im)
#pragma unroll
                        for (int r = 0; r < 4; ++r) {
                            const int slot = (hm * 2 + im) * 2 + (r >> 1);
                            float S1 = i2f22(ac1[in][im][r]);
                            float S2 = i2f22(ac2[in][im][r]);
                            float v = fmaf(S2, (1.0f / 254.0f), S1) * rs[slot] *
                                      ((r & 1) ? cs1 : cs0);
                            float ev = v > 0.0f ? v : (__expf(v) - 1.0f);
                            if (t < 8) accg[slot][r & 1] = fmaf(w, ev, accg[slot][r & 1]);
                            else       accf[slot] = fmaf((r & 1) ? wf1 : wf0, ev, accf[slot]);
                        }
                }
            }
        }
        __syncthreads();
    }

    // cross-warp reduction: warps 4-7 (n 64-127) hand partials to warps 0-3
    float* red = (float*)smem;                  // reuse XA region
    const int rbase = ((wid & 3) * 32 + l) * 24;
    if (wid >= 4) {
#pragma unroll
        for (int r = 0; r < 8; ++r) {
            red[rbase + 2 * r]     = accg[r][0];
            red[rbase + 2 * r + 1] = accg[r][1];
            red[rbase + 16 + r]    = accf[r];
        }
    }
    __syncthreads();
    if (wid < 4) {
        const float bgi = bgv[i], bfi = bfv[i];
#pragma unroll
        for (int r = 0; r < 8; ++r) {
            float g0 = accg[r][0] + red[rbase + 2 * r];
            float g1 = accg[r][1] + red[rbase + 2 * r + 1];
            float vf = accf[r] + red[rbase + 16 + r];
            const int row = b0 + warp_m + (r >> 1) * 16 + (r & 1) * 8 + (l >> 2);
            *reinterpret_cast<float2*>(gout + ((size_t)row * 128 + i) * 8 + 2 * (l & 3)) =
                make_float2(g0 + bgi, g1 + bgi);
            vf += __shfl_xor_sync(0xffffffffu, vf, 1);
            vf += __shfl_xor_sync(0xffffffffu, vf, 2);
            if ((l & 3) == 0) fout[(size_t)row * 128 + i] = vf + bfi;
        }
    }
}

// ---------------- launch ----------------
extern "C" void kernel_launch(void* const* d_in, const int* in_sizes, int n_in,
                              void* d_out, int out_size) {
    (void)in_sizes; (void)n_in; (void)out_size;
    const float* x  = (const float*)d_in[0];
    const float* fw = (const float*)d_in[1];
    const float* gw = (const float*)d_in[2];
    const float* Wf = (const float*)d_in[3];
    const float* bf = (const float*)d_in[4];
    const float* Wg = (const float*)d_in[5];
    const float* bg = (const float*)d_in[6];
    float* out  = (float*)d_out;
    float* fout = out;                      // [B,N]
    float* gout = out + (size_t)B_ * N_;    // [B,N,D]

    static bool attr_set = false;
    if (!attr_set) {
        cudaFuncSetAttribute(prep_w, cudaFuncAttributeMaxDynamicSharedMemorySize, 128 * 132 * 4);
        cudaFuncSetAttribute(sde_main, cudaFuncAttributeMaxDynamicSharedMemorySize, SM_TOT);
        attr_set = true;
    }

    prep_x<<<128, 256>>>(x);
    prep_w<<<dim3(9, 128), 256, 128 * 132 * 4>>>(fw, gw);
    sde_main<<<dim3(4, 128), 256, SM_TOT>>>(Wf, bf, Wg, bg, fout, gout);
}

// round 9
// speedup vs baseline: 2.2099x; 2.2073x over previous
#include <cuda_runtime.h>
#include <cuda_bf16.h>
#include <cstdint>

#define B_ 1024
#define N_ 128
#define H_ 128
#define D_ 8
#define NT 9   // 8 g col-tiles (128 cols) + 1 f tile

// Packed operands (prep kernels write, main reads)
// g_xa: [mtile 8][chunk 16][m 128][k16] bf16 pairs; chunks 0-7 = Xhi, 8-15 = Xlo
__device__ __align__(16) unsigned g_xa[8 * 16 * 128 * 8];          // 512KB
// g_pb: per (node,tile): [chunk 16][n 128][k16] bf16 pairs; chunks 0-7 Whi, 8-15 Wlo
__device__ __align__(16) unsigned g_pb[(size_t)N_ * NT * 16384];   // 75.5MB

// ---------------- helpers ----------------
__device__ __forceinline__ uint32_t smem_u32(const void* p) {
    uint32_t a;
    asm("{ .reg .u64 t; cvta.to.shared.u64 t, %1; cvt.u32.u64 %0, t; }" : "=r"(a) : "l"(p));
    return a;
}
__device__ __forceinline__ unsigned pack_bf16(float f0, float f1, bool lo) {
    __nv_bfloat16 h0 = __float2bfloat16_rn(f0), h1 = __float2bfloat16_rn(f1);
    if (lo) {
        h0 = __float2bfloat16_rn(f0 - __bfloat162float(h0));
        h1 = __float2bfloat16_rn(f1 - __bfloat162float(h1));
    }
    __nv_bfloat162 t = __halves2bfloat162(h0, h1);
    return *reinterpret_cast<unsigned*>(&t);
}
__device__ __forceinline__ float elu1(float x) {
    return x > 0.0f ? x : (__expf(x) - 1.0f);
}

#define CP16(s, g) asm volatile("cp.async.cg.shared.global [%0], [%1], 16;" :: "r"(s), "l"(g))
#define CP_COMMIT() asm volatile("cp.async.commit_group;" ::: "memory")
#define CP_WAIT(n)  asm volatile("cp.async.wait_group %0;" :: "n"(n) : "memory")

#define LDM4(r0, r1, r2, r3, a) \
    asm volatile("ldmatrix.sync.aligned.m8n8.x4.shared.b16 {%0,%1,%2,%3}, [%4];" \
        : "=r"(r0), "=r"(r1), "=r"(r2), "=r"(r3) : "r"(a))

#define MMA16816(c, a, b) \
    asm volatile("mma.sync.aligned.m16n8k16.row.col.f32.bf16.bf16.f32 " \
        "{%0,%1,%2,%3}, {%4,%5,%6,%7}, {%8,%9}, {%0,%1,%2,%3};" \
        : "+f"((c)[0]), "+f"((c)[1]), "+f"((c)[2]), "+f"((c)[3]) \
        : "r"((a)[0]), "r"((a)[1]), "r"((a)[2]), "r"((a)[3]), "r"((b)[0]), "r"((b)[1]))

// ---------------- prep: x -> g_xa (validated R5 version) ----------------
__global__ void prep_x(const float* __restrict__ x) {
    int idx = blockIdx.x * blockDim.x + threadIdx.x;       // one u32 each
    if (idx >= 131072) return;
    int mt = idx >> 14;             // 16384 u32 per m-tile
    int c  = (idx >> 10) & 15;      // chunk 0..15
    int m  = (idx >> 3) & 127;
    int p  = idx & 7;
    int row = mt * 128 + m;
    int kb = (c & 7) * 16 + 2 * p;
    g_xa[idx] = pack_bf16(x[row * 128 + kb], x[row * 128 + kb + 1], c >= 8);
}

// ---------------- prep: weights -> g_pb (validated R5 version) ----------------
__global__ void prep_w(const float* __restrict__ fw, const float* __restrict__ gw) {
    extern __shared__ float s[];               // s[n*132 + k]
    const int t = blockIdx.x, i = blockIdx.y, tid = threadIdx.x;
    const float* src = (t < 8) ? (gw + (size_t)i * 131072 + t * 128)
                               : (fw + (size_t)i * 16384);
    const int stride = (t < 8) ? 1024 : 128;
    for (int idx = tid; idx < 128 * 128; idx += 256) {
        int k = idx >> 7, n = idx & 127;
        s[n * 132 + k] = src[(size_t)k * stride + n];
    }
    __syncthreads();
    unsigned* out = g_pb + (size_t)(i * NT + t) * 16384;
    for (int v = 0; v < 16; ++v) {
        int o = (v * 256 + tid) * 4;           // u32 index of uint4
        int c = o >> 10, n = (o >> 3) & 127, p0 = o & 7;
        int kb = (c & 7) * 16 + 2 * p0;
        bool lo = c >= 8;
        const float* sp = &s[n * 132 + kb];
        uint4 val;
        val.x = pack_bf16(sp[0], sp[1], lo);
        val.y = pack_bf16(sp[2], sp[3], lo);
        val.z = pack_bf16(sp[4], sp[5], lo);
        val.w = pack_bf16(sp[6], sp[7], lo);
        *reinterpret_cast<uint4*>(out + o) = val;
    }
}

// ---------------- main fused kernel ----------------
// grid (8 m-tiles, 128 nodes), 256 threads = 8 warps (2/SMSP).
// Warp tile 32x64: warp_m = (wid&3)*32, warp_n = (wid>>2)*64.
// smem: XA 64KB | B0 64KB | B1 64KB | Wg 512B | Wf 512B
#define SM_XA 0
#define SM_B0 65536
#define SM_WG 196608
#define SM_WF 197120
#define SM_TOT 197632

__global__ __launch_bounds__(256, 1)
void sde_main(const float* __restrict__ Wf, const float* __restrict__ bfv,
              const float* __restrict__ Wg, const float* __restrict__ bgv,
              float* __restrict__ fout, float* __restrict__ gout) {
    extern __shared__ char smem[];
    const uint32_t sb = smem_u32(smem);
    const int tid = threadIdx.x, l = tid & 31, wid = tid >> 5;
    const int i = blockIdx.y, b0 = blockIdx.x * 128;
    const int warp_m = (wid & 3) * 32;
    const int warp_n = (wid >> 2) * 64;
    float* Wg_s = (float*)(smem + SM_WG);
    float* Wf_s = (float*)(smem + SM_WF);

    // stage XA (64KB) + B tile 0 (64KB), one cp.async group
    const char* asrc = (const char*)g_xa + (size_t)blockIdx.x * 65536;
    const char* bsrc = (const char*)(g_pb + (size_t)(i * NT) * 16384);
#pragma unroll
    for (int j = 0; j < 16; ++j) {
        uint32_t off = (uint32_t)(j * 256 + tid) * 16;
        CP16(sb + SM_XA + off, asrc + off);
        CP16(sb + SM_B0 + off, bsrc + off);
    }
    CP_COMMIT();
    if (tid < 128) { Wg_s[tid] = Wg[i * H_ + tid]; Wf_s[tid] = Wf[i * H_ + tid]; }

    const uint32_t aoff = (uint32_t)((warp_m + (l & 15)) * 32 + (l >> 4) * 16);
    const uint32_t boff = (uint32_t)((warp_n + (l & 15)) * 32 + (l >> 4) * 16);

    float accg[4][2], accf[4];
#pragma unroll
    for (int r = 0; r < 4; ++r) { accg[r][0] = 0.f; accg[r][1] = 0.f; accf[r] = 0.f; }

    for (int t = 0; t < NT; ++t) {
        if (t + 1 < NT) {    // prefetch next B tile into other buffer
            uint32_t dst = sb + SM_B0 + ((t + 1) & 1) * 65536;
            const char* src = bsrc + (size_t)(t + 1) * 65536;
#pragma unroll
            for (int j = 0; j < 16; ++j) {
                uint32_t off = (uint32_t)(j * 256 + tid) * 16;
                CP16(dst + off, src + off);
            }
            CP_COMMIT();
            CP_WAIT(1);
        } else {
            CP_WAIT(0);
        }
        __syncthreads();

        const uint32_t bbase = sb + SM_B0 + (t & 1) * 65536;
        float acc[8][2][4];
#pragma unroll
        for (int in = 0; in < 8; ++in)
#pragma unroll
            for (int im = 0; im < 2; ++im)
#pragma unroll
                for (int r = 0; r < 4; ++r) acc[in][im][r] = 0.f;

#pragma unroll
        for (int s = 0; s < 24; ++s) {
            const uint32_t ab = sb + SM_XA + (uint32_t)(((s < 16) ? s : s - 16) * 4096) + aoff;
            const uint32_t bb = bbase + (uint32_t)(((s < 8) ? s : s - 8) * 4096) + boff;
            uint32_t af[2][4], bfr[8][2];
#pragma unroll
            for (int im = 0; im < 2; ++im)
                LDM4(af[im][0], af[im][1], af[im][2], af[im][3], ab + im * 512);
#pragma unroll
            for (int pr = 0; pr < 4; ++pr)
                LDM4(bfr[2 * pr][0], bfr[2 * pr + 1][0],
                     bfr[2 * pr][1], bfr[2 * pr + 1][1], bb + pr * 512);
#pragma unroll
            for (int im = 0; im < 2; ++im)
#pragma unroll
                for (int in = 0; in < 8; ++in)
                    MMA16816(acc[in][im], af[im], bfr[in]);
        }

        // fused epilogue
        if (t < 8) {
            const int hb = t * 16 + (wid >> 2) * 8;
#pragma unroll
            for (int in = 0; in < 8; ++in) {
                const float w = Wg_s[hb + in];
#pragma unroll
                for (int im = 0; im < 2; ++im) {
                    accg[im * 2][0]     = fmaf(w, elu1(acc[in][im][0]), accg[im * 2][0]);
                    accg[im * 2][1]     = fmaf(w, elu1(acc[in][im][1]), accg[im * 2][1]);
                    accg[im * 2 + 1][0] = fmaf(w, elu1(acc[in][im][2]), accg[im * 2 + 1][0]);
                    accg[im * 2 + 1][1] = fmaf(w, elu1(acc[in][im][3]), accg[im * 2 + 1][1]);
                }
            }
        } else {
            const int cb = warp_n + 2 * (l & 3);
#pragma unroll
            for (int in = 0; in < 8; ++in) {
                const float w0 = Wf_s[cb + in * 8], w1 = Wf_s[cb + in * 8 + 1];
#pragma unroll
                for (int im = 0; im < 2; ++im) {
                    accf[im * 2]     += w0 * elu1(acc[in][im][0]) + w1 * elu1(acc[in][im][1]);
                    accf[im * 2 + 1] += w0 * elu1(acc[in][im][2]) + w1 * elu1(acc[in][im][3]);
                }
            }
        }
        __syncthreads();   // everyone done with buffers before overwrite
    }

    // cross-warp reduction: n-warps 4-7 hand partials to warps 0-3
    float* red = (float*)smem;                 // reuse XA region
    const int base = ((wid & 3) * 32 + l) * 12;
    if (wid >= 4) {
#pragma unroll
        for (int r = 0; r < 4; ++r) {
            red[base + r * 2]     = accg[r][0];
            red[base + r * 2 + 1] = accg[r][1];
            red[base + 8 + r]     = accf[r];
        }
    }
    __syncthreads();
    if (wid < 4) {
        const float bgi = bgv[i], bfi = bfv[i];
#pragma unroll
        for (int r = 0; r < 4; ++r) {
            float g0 = accg[r][0] + red[base + r * 2];
            float g1 = accg[r][1] + red[base + r * 2 + 1];
            float vf = accf[r] + red[base + 8 + r];
            const int row = b0 + warp_m + (r >> 1) * 16 + (r & 1) * 8 + (l >> 2);
            *reinterpret_cast<float2*>(gout + ((size_t)row * 128 + i) * 8 + 2 * (l & 3)) =
                make_float2(g0 + bgi, g1 + bgi);
            vf += __shfl_xor_sync(0xffffffffu, vf, 1);
            vf += __shfl_xor_sync(0xffffffffu, vf, 2);
            if ((l & 3) == 0) fout[(size_t)row * 128 + i] = vf + bfi;
        }
    }
}

// ---------------- launch ----------------
extern "C" void kernel_launch(void* const* d_in, const int* in_sizes, int n_in,
                              void* d_out, int out_size) {
    (void)in_sizes; (void)n_in; (void)out_size;
    const float* x  = (const float*)d_in[0];
    const float* fw = (const float*)d_in[1];
    const float* gw = (const float*)d_in[2];
    const float* Wf = (const float*)d_in[3];
    const float* bf = (const float*)d_in[4];
    const float* Wg = (const float*)d_in[5];
    const float* bg = (const float*)d_in[6];
    float* out  = (float*)d_out;
    float* fout = out;                      // [B,N]
    float* gout = out + (size_t)B_ * N_;    // [B,N,D]

    static bool attr_set = false;
    if (!attr_set) {
        cudaFuncSetAttribute(prep_w, cudaFuncAttributeMaxDynamicSharedMemorySize, 128 * 132 * 4);
        cudaFuncSetAttribute(sde_main, cudaFuncAttributeMaxDynamicSharedMemorySize, SM_TOT);
        attr_set = true;
    }

    prep_x<<<512, 256>>>(x);
    prep_w<<<dim3(NT, N_), 256, 128 * 132 * 4>>>(fw, gw);
    sde_main<<<dim3(8, N_), 256, SM_TOT>>>(Wf, bf, Wg, bg, fout, gout);
}

// round 10
// speedup vs baseline: 2.9164x; 1.3197x over previous
#include <cuda_runtime.h>
#include <cuda_fp16.h>
#include <cstdint>

#define B_ 1024
#define N_ 128
#define H_ 128
#define D_ 8
#define NT 9   // 8 g col-tiles (128 cols) + 1 f tile

// Packed operands (prep kernels write, main reads)
// g_xa: [mtile 8][chunk 16][m 128][k16] fp16 pairs; chunks 0-7 = Xhi, 8-15 = Xlo
__device__ __align__(16) unsigned g_xa[8 * 16 * 128 * 8];          // 512KB
// g_pb: per (node,tile): [chunk 8][n 128][k16] fp16 pairs (single-level W)
__device__ __align__(16) unsigned g_pb[(size_t)N_ * NT * 8192];    // 37.7MB

// ---------------- helpers ----------------
__device__ __forceinline__ uint32_t smem_u32(const void* p) {
    uint32_t a;
    asm("{ .reg .u64 t; cvta.to.shared.u64 t, %1; cvt.u32.u64 %0, t; }" : "=r"(a) : "l"(p));
    return a;
}
__device__ __forceinline__ unsigned pack_h2(__half a, __half b) {
    __half2 t = __halves2half2(a, b);
    return *reinterpret_cast<unsigned*>(&t);
}
__device__ __forceinline__ unsigned pack_x(float f0, float f1, bool lo) {
    __half h0 = __float2half_rn(f0), h1 = __float2half_rn(f1);
    if (lo) {
        h0 = __float2half_rn(f0 - __half2float(h0));
        h1 = __float2half_rn(f1 - __half2float(h1));
    }
    return pack_h2(h0, h1);
}
__device__ __forceinline__ float elu1(float x) {
    return x > 0.0f ? x : (__expf(x) - 1.0f);
}

#define CP16(s, g) asm volatile("cp.async.cg.shared.global [%0], [%1], 16;" :: "r"(s), "l"(g))
#define CP_COMMIT() asm volatile("cp.async.commit_group;" ::: "memory")
#define CP_WAIT(n)  asm volatile("cp.async.wait_group %0;" :: "n"(n) : "memory")

#define LDM4(r0, r1, r2, r3, a) \
    asm volatile("ldmatrix.sync.aligned.m8n8.x4.shared.b16 {%0,%1,%2,%3}, [%4];" \
        : "=r"(r0), "=r"(r1), "=r"(r2), "=r"(r3) : "r"(a))

#define MMA16816(c, a, b) \
    asm volatile("mma.sync.aligned.m16n8k16.row.col.f32.f16.f16.f32 " \
        "{%0,%1,%2,%3}, {%4,%5,%6,%7}, {%8,%9}, {%0,%1,%2,%3};" \
        : "+f"((c)[0]), "+f"((c)[1]), "+f"((c)[2]), "+f"((c)[3]) \
        : "r"((a)[0]), "r"((a)[1]), "r"((a)[2]), "r"((a)[3]), "r"((b)[0]), "r"((b)[1]))

// ---------------- prep: x -> g_xa (fp16 hi/lo, R5-validated indexing) ----------
__global__ void prep_x(const float* __restrict__ x) {
    int idx = blockIdx.x * blockDim.x + threadIdx.x;       // one u32 each
    if (idx >= 131072) return;
    int mt = idx >> 14;             // 16384 u32 per m-tile
    int c  = (idx >> 10) & 15;      // chunk 0..15
    int m  = (idx >> 3) & 127;
    int p  = idx & 7;
    int row = mt * 128 + m;
    int kb = (c & 7) * 16 + 2 * p;
    g_xa[idx] = pack_x(x[row * 128 + kb], x[row * 128 + kb + 1], c >= 8);
}

// ---------------- prep: weights -> g_pb (single-level fp16) --------------------
__global__ void prep_w(const float* __restrict__ fw, const float* __restrict__ gw) {
    extern __shared__ float s[];               // s[n*132 + k]
    const int t = blockIdx.x, i = blockIdx.y, tid = threadIdx.x;
    const float* src = (t < 8) ? (gw + (size_t)i * 131072 + t * 128)
                               : (fw + (size_t)i * 16384);
    const int stride = (t < 8) ? 1024 : 128;
    for (int idx = tid; idx < 128 * 128; idx += 256) {
        int k = idx >> 7, n = idx & 127;
        s[n * 132 + k] = src[(size_t)k * stride + n];
    }
    __syncthreads();
    unsigned* out = g_pb + (size_t)(i * NT + t) * 8192;
    for (int v = 0; v < 8; ++v) {
        int o = (v * 256 + tid) * 4;           // u32 index of uint4
        int c = o >> 10, n = (o >> 3) & 127, p0 = o & 7;
        int kb = c * 16 + 2 * p0;
        const float* sp = &s[n * 132 + kb];
        uint4 val;
        val.x = pack_h2(__float2half_rn(sp[0]), __float2half_rn(sp[1]));
        val.y = pack_h2(__float2half_rn(sp[2]), __float2half_rn(sp[3]));
        val.z = pack_h2(__float2half_rn(sp[4]), __float2half_rn(sp[5]));
        val.w = pack_h2(__float2half_rn(sp[6]), __float2half_rn(sp[7]));
        *reinterpret_cast<uint4*>(out + o) = val;
    }
}

// ---------------- main fused kernel ----------------
// grid (8 m-tiles, 128 nodes), 256 threads = 8 warps (2/SMSP).
// Warp tile 32x64: warp_m = (wid&3)*32, warp_n = (wid>>2)*64.
// smem: XA 64KB | B0 32KB | B1 32KB | Wg 512B | Wf 512B
#define SM_XA 0
#define SM_B0 65536
#define SM_WG 131072
#define SM_WF 131584
#define SM_TOT 132096

__global__ __launch_bounds__(256, 1)
void sde_main(const float* __restrict__ Wf, const float* __restrict__ bfv,
              const float* __restrict__ Wg, const float* __restrict__ bgv,
              float* __restrict__ fout, float* __restrict__ gout) {
    extern __shared__ char smem[];
    const uint32_t sb = smem_u32(smem);
    const int tid = threadIdx.x, l = tid & 31, wid = tid >> 5;
    const int i = blockIdx.y, b0 = blockIdx.x * 128;
    const int warp_m = (wid & 3) * 32;
    const int warp_n = (wid >> 2) * 64;
    float* Wg_s = (float*)(smem + SM_WG);
    float* Wf_s = (float*)(smem + SM_WF);

    // stage XA (64KB) + B tile 0 (32KB), one cp.async group
    const char* asrc = (const char*)g_xa + (size_t)blockIdx.x * 65536;
    const char* bsrc = (const char*)(g_pb + (size_t)(i * NT) * 8192);
#pragma unroll
    for (int j = 0; j < 16; ++j) {
        uint32_t off = (uint32_t)(j * 256 + tid) * 16;
        CP16(sb + SM_XA + off, asrc + off);
        if (j < 8) CP16(sb + SM_B0 + off, bsrc + off);
    }
    CP_COMMIT();
    if (tid < 128) { Wg_s[tid] = Wg[i * H_ + tid]; Wf_s[tid] = Wf[i * H_ + tid]; }

    const uint32_t aoff = (uint32_t)((warp_m + (l & 15)) * 32 + (l >> 4) * 16);
    const uint32_t boff = (uint32_t)((warp_n + (l & 15)) * 32 + (l >> 4) * 16);

    float accg[4][2], accf[4];
#pragma unroll
    for (int r = 0; r < 4; ++r) { accg[r][0] = 0.f; accg[r][1] = 0.f; accf[r] = 0.f; }

    for (int t = 0; t < NT; ++t) {
        if (t + 1 < NT) {    // prefetch next B tile into other buffer
            uint32_t dst = sb + SM_B0 + ((t + 1) & 1) * 32768;
            const char* src = bsrc + (size_t)(t + 1) * 32768;
#pragma unroll
            for (int j = 0; j < 8; ++j) {
                uint32_t off = (uint32_t)(j * 256 + tid) * 16;
                CP16(dst + off, src + off);
            }
            CP_COMMIT();
            CP_WAIT(1);
        } else {
            CP_WAIT(0);
        }
        __syncthreads();

        const uint32_t bbase = sb + SM_B0 + (t & 1) * 32768;
        float acc[8][2][4];
#pragma unroll
        for (int in = 0; in < 8; ++in)
#pragma unroll
            for (int im = 0; im < 2; ++im)
#pragma unroll
                for (int r = 0; r < 4; ++r) acc[in][im][r] = 0.f;

#pragma unroll
        for (int s = 0; s < 16; ++s) {
            const uint32_t ab = sb + SM_XA + (uint32_t)(s * 4096) + aoff;
            const uint32_t bb = bbase + (uint32_t)((s & 7) * 4096) + boff;
            uint32_t af[2][4], bfr[8][2];
#pragma unroll
            for (int im = 0; im < 2; ++im)
                LDM4(af[im][0], af[im][1], af[im][2], af[im][3], ab + im * 512);
#pragma unroll
            for (int pr = 0; pr < 4; ++pr)
                LDM4(bfr[2 * pr][0], bfr[2 * pr + 1][0],
                     bfr[2 * pr][1], bfr[2 * pr + 1][1], bb + pr * 512);
#pragma unroll
            for (int im = 0; im < 2; ++im)
#pragma unroll
                for (int in = 0; in < 8; ++in)
                    MMA16816(acc[in][im], af[im], bfr[in]);
        }

        // fused epilogue
        if (t < 8) {
            const int hb = t * 16 + (wid >> 2) * 8;
#pragma unroll
            for (int in = 0; in < 8; ++in) {
                const float w = Wg_s[hb + in];
#pragma unroll
                for (int im = 0; im < 2; ++im) {
                    accg[im * 2][0]     = fmaf(w, elu1(acc[in][im][0]), accg[im * 2][0]);
                    accg[im * 2][1]     = fmaf(w, elu1(acc[in][im][1]), accg[im * 2][1]);
                    accg[im * 2 + 1][0] = fmaf(w, elu1(acc[in][im][2]), accg[im * 2 + 1][0]);
                    accg[im * 2 + 1][1] = fmaf(w, elu1(acc[in][im][3]), accg[im * 2 + 1][1]);
                }
            }
        } else {
            const int cb = warp_n + 2 * (l & 3);
#pragma unroll
            for (int in = 0; in < 8; ++in) {
                const float w0 = Wf_s[cb + in * 8], w1 = Wf_s[cb + in * 8 + 1];
#pragma unroll
                for (int im = 0; im < 2; ++im) {
                    accf[im * 2]     += w0 * elu1(acc[in][im][0]) + w1 * elu1(acc[in][im][1]);
                    accf[im * 2 + 1] += w0 * elu1(acc[in][im][2]) + w1 * elu1(acc[in][im][3]);
                }
            }
        }
        __syncthreads();   // everyone done with buffers before overwrite
    }

    // cross-warp reduction: n-warps 4-7 hand partials to warps 0-3
    float* red = (float*)smem;                 // reuse XA region
    const int base = ((wid & 3) * 32 + l) * 12;
    if (wid >= 4) {
#pragma unroll
        for (int r = 0; r < 4; ++r) {
            red[base + r * 2]     = accg[r][0];
            red[base + r * 2 + 1] = accg[r][1];
            red[base + 8 + r]     = accf[r];
        }
    }
    __syncthreads();
    if (wid < 4) {
        const float bgi = bgv[i], bfi = bfv[i];
#pragma unroll
        for (int r = 0; r < 4; ++r) {
            float g0 = accg[r][0] + red[base + r * 2];
            float g1 = accg[r][1] + red[base + r * 2 + 1];
            float vf = accf[r] + red[base + 8 + r];
            const int row = b0 + warp_m + (r >> 1) * 16 + (r & 1) * 8 + (l >> 2);
            *reinterpret_cast<float2*>(gout + ((size_t)row * 128 + i) * 8 + 2 * (l & 3)) =
                make_float2(g0 + bgi, g1 + bgi);
            vf += __shfl_xor_sync(0xffffffffu, vf, 1);
            vf += __shfl_xor_sync(0xffffffffu, vf, 2);
            if ((l & 3) == 0) fout[(size_t)row * 128 + i] = vf + bfi;
        }
    }
}

// ---------------- launch ----------------
extern "C" void kernel_launch(void* const* d_in, const int* in_sizes, int n_in,
                              void* d_out, int out_size) {
    (void)in_sizes; (void)n_in; (void)out_size;
    const float* x  = (const float*)d_in[0];
    const float* fw = (const float*)d_in[1];
    const float* gw = (const float*)d_in[2];
    const float* Wf = (const float*)d_in[3];
    const float* bf = (const float*)d_in[4];
    const float* Wg = (const float*)d_in[5];
    const float* bg = (const float*)d_in[6];
    float* out  = (float*)d_out;
    float* fout = out;                      // [B,N]
    float* gout = out + (size_t)B_ * N_;    // [B,N,D]

    static bool attr_set = false;
    if (!attr_set) {
        cudaFuncSetAttribute(prep_w, cudaFuncAttributeMaxDynamicSharedMemorySize, 128 * 132 * 4);
        cudaFuncSetAttribute(sde_main, cudaFuncAttributeMaxDynamicSharedMemorySize, SM_TOT);
        attr_set = true;
    }

    prep_x<<<512, 256>>>(x);
    prep_w<<<dim3(NT, N_), 256, 128 * 132 * 4>>>(fw, gw);
    sde_main<<<dim3(8, N_), 256, SM_TOT>>>(Wf, bf, Wg, bg, fout, gout);
}

// round 11
// speedup vs baseline: 4.7460x; 1.6273x over previous
#include <cuda_runtime.h>
#include <cuda_fp16.h>
#include <cstdint>

#define B_ 1024
#define N_ 128
#define H_ 128
#define D_ 8
#define NT 9   // 8 g col-tiles (128 cols) + 1 f tile

// Packed operands (prep kernels write, main reads)
// g_xa: [mtile 8][chunk 8][m 128][k16] fp16 pairs (single-level X)
__device__ __align__(16) unsigned g_xa[8 * 8 * 128 * 8];           // 256KB
// g_pb: per (node,tile): [chunk 8][n 128][k16] fp16 pairs (single-level W)
__device__ __align__(16) unsigned g_pb[(size_t)N_ * NT * 8192];    // 37.7MB

// ---------------- helpers ----------------
__device__ __forceinline__ uint32_t smem_u32(const void* p) {
    uint32_t a;
    asm("{ .reg .u64 t; cvta.to.shared.u64 t, %1; cvt.u32.u64 %0, t; }" : "=r"(a) : "l"(p));
    return a;
}
__device__ __forceinline__ unsigned pack_h2(__half a, __half b) {
    __half2 t = __halves2half2(a, b);
    return *reinterpret_cast<unsigned*>(&t);
}
__device__ __forceinline__ float elu1(float x) {
    return x > 0.0f ? x : (__expf(x) - 1.0f);
}

#define CP16(s, g) asm volatile("cp.async.cg.shared.global [%0], [%1], 16;" :: "r"(s), "l"(g))
#define CP_COMMIT() asm volatile("cp.async.commit_group;" ::: "memory")
#define CP_WAIT(n)  asm volatile("cp.async.wait_group %0;" :: "n"(n) : "memory")

#define LDM4(r0, r1, r2, r3, a) \
    asm volatile("ldmatrix.sync.aligned.m8n8.x4.shared.b16 {%0,%1,%2,%3}, [%4];" \
        : "=r"(r0), "=r"(r1), "=r"(r2), "=r"(r3) : "r"(a))

#define MMA16816(c, a, b) \
    asm volatile("mma.sync.aligned.m16n8k16.row.col.f32.f16.f16.f32 " \
        "{%0,%1,%2,%3}, {%4,%5,%6,%7}, {%8,%9}, {%0,%1,%2,%3};" \
        : "+f"((c)[0]), "+f"((c)[1]), "+f"((c)[2]), "+f"((c)[3]) \
        : "r"((a)[0]), "r"((a)[1]), "r"((a)[2]), "r"((a)[3]), "r"((b)[0]), "r"((b)[1]))

// ---------------- prep: x -> g_xa (single-level fp16) ----------------
__global__ void prep_x(const float* __restrict__ x) {
    int idx = blockIdx.x * blockDim.x + threadIdx.x;       // one u32 each
    if (idx >= 65536) return;
    int mt = idx >> 13;             // 8192 u32 per m-tile
    int c  = (idx >> 10) & 7;       // chunk 0..7
    int m  = (idx >> 3) & 127;
    int p  = idx & 7;
    int row = mt * 128 + m;
    int kb = c * 16 + 2 * p;
    g_xa[idx] = pack_h2(__float2half_rn(x[row * 128 + kb]),
                        __float2half_rn(x[row * 128 + kb + 1]));
}

// ---------------- prep: weights -> g_pb (single-level fp16) --------------------
__global__ void prep_w(const float* __restrict__ fw, const float* __restrict__ gw) {
    extern __shared__ float s[];               // s[n*132 + k]
    const int t = blockIdx.x, i = blockIdx.y, tid = threadIdx.x;
    const float* src = (t < 8) ? (gw + (size_t)i * 131072 + t * 128)
                               : (fw + (size_t)i * 16384);
    const int stride = (t < 8) ? 1024 : 128;
    for (int idx = tid; idx < 128 * 128; idx += 256) {
        int k = idx >> 7, n = idx & 127;
        s[n * 132 + k] = src[(size_t)k * stride + n];
    }
    __syncthreads();
    unsigned* out = g_pb + (size_t)(i * NT + t) * 8192;
    for (int v = 0; v < 8; ++v) {
        int o = (v * 256 + tid) * 4;           // u32 index of uint4
        int c = o >> 10, n = (o >> 3) & 127, p0 = o & 7;
        int kb = c * 16 + 2 * p0;
        const float* sp = &s[n * 132 + kb];
        uint4 val;
        val.x = pack_h2(__float2half_rn(sp[0]), __float2half_rn(sp[1]));
        val.y = pack_h2(__float2half_rn(sp[2]), __float2half_rn(sp[3]));
        val.z = pack_h2(__float2half_rn(sp[4]), __float2half_rn(sp[5]));
        val.w = pack_h2(__float2half_rn(sp[6]), __float2half_rn(sp[7]));
        *reinterpret_cast<uint4*>(out + o) = val;
    }
}

// ---------------- main fused kernel ----------------
// grid (8 m-tiles, 128 nodes), 256 threads = 8 warps (2/SMSP).
// Warp tile 32x64: warp_m = (wid&3)*32, warp_n = (wid>>2)*64.
// smem: XA 32KB | B0 32KB | B1 32KB | Wg 512B | Wf 512B  (~100KB, 2 CTAs/SM)
#define SM_XA 0
#define SM_B0 32768
#define SM_WG 98304
#define SM_WF 98816
#define SM_TOT 99328

__global__ __launch_bounds__(256, 2)
void sde_main(const float* __restrict__ Wf, const float* __restrict__ bfv,
              const float* __restrict__ Wg, const float* __restrict__ bgv,
              float* __restrict__ fout, float* __restrict__ gout) {
    extern __shared__ char smem[];
    const uint32_t sb = smem_u32(smem);
    const int tid = threadIdx.x, l = tid & 31, wid = tid >> 5;
    const int i = blockIdx.y, b0 = blockIdx.x * 128;
    const int warp_m = (wid & 3) * 32;
    const int warp_n = (wid >> 2) * 64;
    float* Wg_s = (float*)(smem + SM_WG);
    float* Wf_s = (float*)(smem + SM_WF);

    // stage XA (32KB) + B tile 0 (32KB), one cp.async group
    const char* asrc = (const char*)g_xa + (size_t)blockIdx.x * 32768;
    const char* bsrc = (const char*)(g_pb + (size_t)(i * NT) * 8192);
#pragma unroll
    for (int j = 0; j < 8; ++j) {
        uint32_t off = (uint32_t)(j * 256 + tid) * 16;
        CP16(sb + SM_XA + off, asrc + off);
        CP16(sb + SM_B0 + off, bsrc + off);
    }
    CP_COMMIT();
    if (tid < 128) { Wg_s[tid] = Wg[i * H_ + tid]; Wf_s[tid] = Wf[i * H_ + tid]; }

    const uint32_t aoff = (uint32_t)((warp_m + (l & 15)) * 32 + (l >> 4) * 16);
    const uint32_t boff = (uint32_t)((warp_n + (l & 15)) * 32 + (l >> 4) * 16);

    float accg[4][2], accf[4];
#pragma unroll
    for (int r = 0; r < 4; ++r) { accg[r][0] = 0.f; accg[r][1] = 0.f; accf[r] = 0.f; }

    for (int t = 0; t < NT; ++t) {
        if (t + 1 < NT) {    // prefetch next B tile into other buffer
            uint32_t dst = sb + SM_B0 + ((t + 1) & 1) * 32768;
            const char* src = bsrc + (size_t)(t + 1) * 32768;
#pragma unroll
            for (int j = 0; j < 8; ++j) {
                uint32_t off = (uint32_t)(j * 256 + tid) * 16;
                CP16(dst + off, src + off);
            }
            CP_COMMIT();
            CP_WAIT(1);
        } else {
            CP_WAIT(0);
        }
        __syncthreads();

        const uint32_t bbase = sb + SM_B0 + (t & 1) * 32768;
        float acc[8][2][4];
#pragma unroll
        for (int in = 0; in < 8; ++in)
#pragma unroll
            for (int im = 0; im < 2; ++im)
#pragma unroll
                for (int r = 0; r < 4; ++r) acc[in][im][r] = 0.f;

#pragma unroll
        for (int s = 0; s < 8; ++s) {
            const uint32_t ab = sb + SM_XA + (uint32_t)(s * 4096) + aoff;
            const uint32_t bb = bbase + (uint32_t)(s * 4096) + boff;
            uint32_t af[2][4], bfr[8][2];
#pragma unroll
            for (int im = 0; im < 2; ++im)
                LDM4(af[im][0], af[im][1], af[im][2], af[im][3], ab + im * 512);
#pragma unroll
            for (int pr = 0; pr < 4; ++pr)
                LDM4(bfr[2 * pr][0], bfr[2 * pr + 1][0],
                     bfr[2 * pr][1], bfr[2 * pr + 1][1], bb + pr * 512);
#pragma unroll
            for (int im = 0; im < 2; ++im)
#pragma unroll
                for (int in = 0; in < 8; ++in)
                    MMA16816(acc[in][im], af[im], bfr[in]);
        }

        // fused epilogue
        if (t < 8) {
            const int hb = t * 16 + (wid >> 2) * 8;
#pragma unroll
            for (int in = 0; in < 8; ++in) {
                const float w = Wg_s[hb + in];
#pragma unroll
                for (int im = 0; im < 2; ++im) {
                    accg[im * 2][0]     = fmaf(w, elu1(acc[in][im][0]), accg[im * 2][0]);
                    accg[im * 2][1]     = fmaf(w, elu1(acc[in][im][1]), accg[im * 2][1]);
                    accg[im * 2 + 1][0] = fmaf(w, elu1(acc[in][im][2]), accg[im * 2 + 1][0]);
                    accg[im * 2 + 1][1] = fmaf(w, elu1(acc[in][im][3]), accg[im * 2 + 1][1]);
                }
            }
        } else {
            const int cb = warp_n + 2 * (l & 3);
#pragma unroll
            for (int in = 0; in < 8; ++in) {
                const float w0 = Wf_s[cb + in * 8], w1 = Wf_s[cb + in * 8 + 1];
#pragma unroll
                for (int im = 0; im < 2; ++im) {
                    accf[im * 2]     += w0 * elu1(acc[in][im][0]) + w1 * elu1(acc[in][im][1]);
                    accf[im * 2 + 1] += w0 * elu1(acc[in][im][2]) + w1 * elu1(acc[in][im][3]);
                }
            }
        }
        __syncthreads();   // everyone done with buffers before overwrite
    }

    // cross-warp reduction: n-warps 4-7 hand partials to warps 0-3
    float* red = (float*)smem;                 // reuse XA region
    const int base = ((wid & 3) * 32 + l) * 12;
    if (wid >= 4) {
#pragma unroll
        for (int r = 0; r < 4; ++r) {
            red[base + r * 2]     = accg[r][0];
            red[base + r * 2 + 1] = accg[r][1];
            red[base + 8 + r]     = accf[r];
        }
    }
    __syncthreads();
    if (wid < 4) {
        const float bgi = bgv[i], bfi = bfv[i];
#pragma unroll
        for (int r = 0; r < 4; ++r) {
            float g0 = accg[r][0] + red[base + r * 2];
            float g1 = accg[r][1] + red[base + r * 2 + 1];
            float vf = accf[r] + red[base + 8 + r];
            const int row = b0 + warp_m + (r >> 1) * 16 + (r & 1) * 8 + (l >> 2);
            *reinterpret_cast<float2*>(gout + ((size_t)row * 128 + i) * 8 + 2 * (l & 3)) =
                make_float2(g0 + bgi, g1 + bgi);
            vf += __shfl_xor_sync(0xffffffffu, vf, 1);
            vf += __shfl_xor_sync(0xffffffffu, vf, 2);
            if ((l & 3) == 0) fout[(size_t)row * 128 + i] = vf + bfi;
        }
    }
}

// ---------------- launch ----------------
extern "C" void kernel_launch(void* const* d_in, const int* in_sizes, int n_in,
                              void* d_out, int out_size) {
    (void)in_sizes; (void)n_in; (void)out_size;
    const float* x  = (const float*)d_in[0];
    const float* fw = (const float*)d_in[1];
    const float* gw = (const float*)d_in[2];
    const float* Wf = (const float*)d_in[3];
    const float* bf = (const float*)d_in[4];
    const float* Wg = (const float*)d_in[5];
    const float* bg = (const float*)d_in[6];
    float* out  = (float*)d_out;
    float* fout = out;                      // [B,N]
    float* gout = out + (size_t)B_ * N_;    // [B,N,D]

    static bool attr_set = false;
    if (!attr_set) {
        cudaFuncSetAttribute(prep_w, cudaFuncAttributeMaxDynamicSharedMemorySize, 128 * 132 * 4);
        cudaFuncSetAttribute(sde_main, cudaFuncAttributeMaxDynamicSharedMemorySize, SM_TOT);
        attr_set = true;
    }

    prep_x<<<256, 256>>>(x);
    prep_w<<<dim3(NT, N_), 256, 128 * 132 * 4>>>(fw, gw);
    sde_main<<<dim3(8, N_), 256, SM_TOT>>>(Wf, bf, Wg, bg, fout, gout);
}

// round 12
// speedup vs baseline: 5.9098x; 1.2452x over previous
#include <cuda_runtime.h>
#include <cuda_fp16.h>
#include <cstdint>

#define B_ 1024
#define N_ 128
#define H_ 128
#define D_ 8
#define NT 9   // 8 g col-tiles (128 cols) + 1 f tile

// Packed X operand (prep_x writes, main reads)
// g_xa: [mtile 8][chunk 8][m 128][k16] fp16 pairs (single-level X)
__device__ __align__(16) unsigned g_xa[8 * 8 * 128 * 8];           // 256KB

// ---------------- helpers ----------------
__device__ __forceinline__ uint32_t smem_u32(const void* p) {
    uint32_t a;
    asm("{ .reg .u64 t; cvta.to.shared.u64 t, %1; cvt.u32.u64 %0, t; }" : "=r"(a) : "l"(p));
    return a;
}
__device__ __forceinline__ unsigned pack_h2(__half a, __half b) {
    __half2 t = __halves2half2(a, b);
    return *reinterpret_cast<unsigned*>(&t);
}
__device__ __forceinline__ float elu1(float x) {
    return x > 0.0f ? x : (__expf(x) - 1.0f);
}

#define CP16(s, g) asm volatile("cp.async.cg.shared.global [%0], [%1], 16;" :: "r"(s), "l"(g))
#define CP_COMMIT() asm volatile("cp.async.commit_group;" ::: "memory")
#define CP_WAIT(n)  asm volatile("cp.async.wait_group %0;" :: "n"(n) : "memory")

#define LDM4(r0, r1, r2, r3, a) \
    asm volatile("ldmatrix.sync.aligned.m8n8.x4.shared.b16 {%0,%1,%2,%3}, [%4];" \
        : "=r"(r0), "=r"(r1), "=r"(r2), "=r"(r3) : "r"(a))

#define LDM4T(r0, r1, r2, r3, a) \
    asm volatile("ldmatrix.sync.aligned.m8n8.x4.trans.shared.b16 {%0,%1,%2,%3}, [%4];" \
        : "=r"(r0), "=r"(r1), "=r"(r2), "=r"(r3) : "r"(a))

#define MMA16816(c, a, b) \
    asm volatile("mma.sync.aligned.m16n8k16.row.col.f32.f16.f16.f32 " \
        "{%0,%1,%2,%3}, {%4,%5,%6,%7}, {%8,%9}, {%0,%1,%2,%3};" \
        : "+f"((c)[0]), "+f"((c)[1]), "+f"((c)[2]), "+f"((c)[3]) \
        : "r"((a)[0]), "r"((a)[1]), "r"((a)[2]), "r"((a)[3]), "r"((b)[0]), "r"((b)[1]))

// ---------------- prep: x -> g_xa (single-level fp16) ----------------
__global__ void prep_x(const float* __restrict__ x) {
    int idx = blockIdx.x * blockDim.x + threadIdx.x;       // one u32 each
    if (idx >= 65536) return;
    int mt = idx >> 13;             // 8192 u32 per m-tile
    int c  = (idx >> 10) & 7;       // chunk 0..7
    int m  = (idx >> 3) & 127;
    int p  = idx & 7;
    int row = mt * 128 + m;
    int kb = c * 16 + 2 * p;
    g_xa[idx] = pack_h2(__float2half_rn(x[row * 128 + kb]),
                        __float2half_rn(x[row * 128 + kb + 1]));
}

// ---------------- main fused kernel ----------------
// grid (8 m-tiles, 128 nodes), 256 threads = 8 warps (2/SMSP).
// Warp tile 32x64: warp_m = (wid&3)*32, warp_n = (wid>>2)*64.
// B staged in-kernel from fp32 weights: smem layout [k][n] fp16, 256B rows,
// XOR-16B swizzle; B fragments via ldmatrix.trans.
// smem: B0 32KB | B1 32KB | XA 32KB | Wg 512B | Wf 512B  (~97KB, 2 CTAs/SM)
#define SM_B0 0
#define SM_B1 32768
#define SM_XA 65536
#define SM_WG 98304
#define SM_WF 98816
#define SM_TOT 99328

__global__ __launch_bounds__(256, 2)
void sde_main(const float* __restrict__ fw, const float* __restrict__ gw,
              const float* __restrict__ Wf, const float* __restrict__ bfv,
              const float* __restrict__ Wg, const float* __restrict__ bgv,
              float* __restrict__ fout, float* __restrict__ gout) {
    extern __shared__ char smem[];
    const uint32_t sb = smem_u32(smem);
    const int tid = threadIdx.x, l = tid & 31, wid = tid >> 5;
    const int i = blockIdx.y, b0 = blockIdx.x * 128;
    const int warp_m = (wid & 3) * 32;
    const int warp_n = (wid >> 2) * 64;
    float* Wg_s = (float*)(smem + SM_WG);
    float* Wf_s = (float*)(smem + SM_WF);

    // staging constants: warp wid stages k-row (pass*8 + wid), lane covers 4 cols
    const int wrow = wid;                       // k-row offset within pass group
    const int ncol = (l) * 4;                   // fp32 column base for this lane
    const uint32_t swb = (uint32_t)((l * 8) ^ (wrow << 4));  // swizzled STS byte off in row

    // XA via cp.async (32KB)
    const char* asrc = (const char*)g_xa + (size_t)blockIdx.x * 32768;
#pragma unroll
    for (int j = 0; j < 8; ++j) {
        uint32_t off = (uint32_t)(j * 256 + tid) * 16;
        CP16(sb + SM_XA + off, asrc + off);
    }
    CP_COMMIT();

    // pre-stage B tile 0 (g tile 0: cols 0..127, row stride 1024)
    {
        const float* w0 = gw + (size_t)i * 131072;
#pragma unroll
        for (int pb = 0; pb < 4; ++pb) {
            float4 v[4];
#pragma unroll
            for (int q = 0; q < 4; ++q) {
                int p = pb * 4 + q, k = p * 8 + wrow;
                v[q] = *reinterpret_cast<const float4*>(w0 + (size_t)k * 1024 + ncol);
            }
#pragma unroll
            for (int q = 0; q < 4; ++q) {
                int p = pb * 4 + q, k = p * 8 + wrow;
                uint2 h;
                h.x = pack_h2(__float2half_rn(v[q].x), __float2half_rn(v[q].y));
                h.y = pack_h2(__float2half_rn(v[q].z), __float2half_rn(v[q].w));
                *reinterpret_cast<uint2*>(smem + SM_B0 + k * 256 + swb) = h;
            }
        }
    }
    if (tid < 128) { Wg_s[tid] = Wg[i * H_ + tid]; Wf_s[tid] = Wf[i * H_ + tid]; }
    CP_WAIT(0);
    __syncthreads();

    // fragment addressing constants
    const uint32_t aoff = (uint32_t)((warp_m + (l & 15)) * 32 + (l >> 4) * 16);
    const int kl   = (l & 7) + ((l >> 4) << 3);     // k-row within 16 for this lane
    const int jofs = (l >> 3) & 1;                  // n-block parity within LDM4T
    const int swl  = (l & 7) << 4;                  // swizzle term for LDM addresses

    float accg[4][2], accf[4];
#pragma unroll
    for (int r = 0; r < 4; ++r) { accg[r][0] = 0.f; accg[r][1] = 0.f; accf[r] = 0.f; }

    for (int t = 0; t < NT; ++t) {
        const uint32_t bbase = (uint32_t)((t & 1) ? SM_B1 : SM_B0);
        const uint32_t sbase = (uint32_t)((t & 1) ? SM_B0 : SM_B1);   // staging target (t+1)
        const bool stg = (t + 1 < NT);
        const float* wsrc = nullptr;
        int wstr = 0;
        if (stg) {
            if (t + 1 < 8) { wsrc = gw + (size_t)i * 131072 + (t + 1) * 128; wstr = 1024; }
            else           { wsrc = fw + (size_t)i * 16384;                  wstr = 128; }
        }

        float acc[8][2][4];
#pragma unroll
        for (int in = 0; in < 8; ++in)
#pragma unroll
            for (int im = 0; im < 2; ++im)
#pragma unroll
                for (int r = 0; r < 4; ++r) acc[in][im][r] = 0.f;

        float4 pa[2], pb2[2];

#pragma unroll
        for (int s = 0; s < 8; ++s) {
            // ---- staged W conversion for tile t+1 (lookahead 2 steps) ----
            if (stg) {
                if (s >= 2) {   // STS passes issued at step s-2
                    int p0 = 2 * (s - 2), k0s = p0 * 8 + wrow;
                    uint2 h;
                    h.x = pack_h2(__float2half_rn(pa[s & 1].x), __float2half_rn(pa[s & 1].y));
                    h.y = pack_h2(__float2half_rn(pa[s & 1].z), __float2half_rn(pa[s & 1].w));
                    *reinterpret_cast<uint2*>(smem + sbase + k0s * 256 + swb) = h;
                    int k1s = k0s + 8;
                    h.x = pack_h2(__float2half_rn(pb2[s & 1].x), __float2half_rn(pb2[s & 1].y));
                    h.y = pack_h2(__float2half_rn(pb2[s & 1].z), __float2half_rn(pb2[s & 1].w));
                    *reinterpret_cast<uint2*>(smem + sbase + k1s * 256 + swb) = h;
                }
                {               // LDG passes 2s, 2s+1
                    int k0s = (2 * s) * 8 + wrow;
                    pa[s & 1]  = *reinterpret_cast<const float4*>(wsrc + (size_t)k0s * wstr + ncol);
                    pb2[s & 1] = *reinterpret_cast<const float4*>(wsrc + (size_t)(k0s + 8) * wstr + ncol);
                }
            }

            // ---- MMA step ----
            const uint32_t ab = sb + SM_XA + (uint32_t)(s * 4096) + aoff;
            uint32_t af[2][4], bfr[8][2];
#pragma unroll
            for (int im = 0; im < 2; ++im)
                LDM4(af[im][0], af[im][1], af[im][2], af[im][3], ab + im * 512);
#pragma unroll
            for (int p = 0; p < 4; ++p) {
                uint32_t kk = (uint32_t)(s * 16 + kl);
                uint32_t roff = (uint32_t)(((warp_n + p * 16 + jofs * 8) * 2) ^ swl);
                LDM4T(bfr[2 * p][0], bfr[2 * p + 1][0],
                      bfr[2 * p][1], bfr[2 * p + 1][1],
                      sb + bbase + kk * 256 + roff);
            }
#pragma unroll
            for (int im = 0; im < 2; ++im)
#pragma unroll
                for (int in = 0; in < 8; ++in)
                    MMA16816(acc[in][im], af[im], bfr[in]);
        }

        // flush staged passes issued at steps 6,7 (passes 12..15)
        if (stg) {
#pragma unroll
            for (int q = 0; q < 2; ++q) {
                int p0 = 12 + 2 * q, k0s = p0 * 8 + wrow;
                uint2 h;
                h.x = pack_h2(__float2half_rn(pa[q].x), __float2half_rn(pa[q].y));
                h.y = pack_h2(__float2half_rn(pa[q].z), __float2half_rn(pa[q].w));
                *reinterpret_cast<uint2*>(smem + sbase + k0s * 256 + swb) = h;
                int k1s = k0s + 8;
                h.x = pack_h2(__float2half_rn(pb2[q].x), __float2half_rn(pb2[q].y));
                h.y = pack_h2(__float2half_rn(pb2[q].z), __float2half_rn(pb2[q].w));
                *reinterpret_cast<uint2*>(smem + sbase + k1s * 256 + swb) = h;
            }
        }

        // fused epilogue
        if (t < 8) {
            const int hb = t * 16 + (wid >> 2) * 8;
#pragma unroll
            for (int in = 0; in < 8; ++in) {
                const float w = Wg_s[hb + in];
#pragma unroll
                for (int im = 0; im < 2; ++im) {
                    accg[im * 2][0]     = fmaf(w, elu1(acc[in][im][0]), accg[im * 2][0]);
                    accg[im * 2][1]     = fmaf(w, elu1(acc[in][im][1]), accg[im * 2][1]);
                    accg[im * 2 + 1][0] = fmaf(w, elu1(acc[in][im][2]), accg[im * 2 + 1][0]);
                    accg[im * 2 + 1][1] = fmaf(w, elu1(acc[in][im][3]), accg[im * 2 + 1][1]);
                }
            }
        } else {
            const int cb = warp_n + 2 * (l & 3);
#pragma unroll
            for (int in = 0; in < 8; ++in) {
                const float w0 = Wf_s[cb + in * 8], w1 = Wf_s[cb + in * 8 + 1];
#pragma unroll
                for (int im = 0; im < 2; ++im) {
                    accf[im * 2]     += w0 * elu1(acc[in][im][0]) + w1 * elu1(acc[in][im][1]);
                    accf[im * 2 + 1] += w0 * elu1(acc[in][im][2]) + w1 * elu1(acc[in][im][3]);
                }
            }
        }
        __syncthreads();   // staged buffer complete + everyone done reading bbase
    }

    // cross-warp reduction: n-warps 4-7 hand partials to warps 0-3
    float* red = (float*)smem;                 // reuse B region
    const int base = ((wid & 3) * 32 + l) * 12;
    if (wid >= 4) {
#pragma unroll
        for (int r = 0; r < 4; ++r) {
            red[base + r * 2]     = accg[r][0];
            red[base + r * 2 + 1] = accg[r][1];
            red[base + 8 + r]     = accf[r];
        }
    }
    __syncthreads();
    if (wid < 4) {
        const float bgi = bgv[i], bfi = bfv[i];
#pragma unroll
        for (int r = 0; r < 4; ++r) {
            float g0 = accg[r][0] + red[base + r * 2];
            float g1 = accg[r][1] + red[base + r * 2 + 1];
            float vf = accf[r] + red[base + 8 + r];
            const int row = b0 + warp_m + (r >> 1) * 16 + (r & 1) * 8 + (l >> 2);
            *reinterpret_cast<float2*>(gout + ((size_t)row * 128 + i) * 8 + 2 * (l & 3)) =
                make_float2(g0 + bgi, g1 + bgi);
            vf += __shfl_xor_sync(0xffffffffu, vf, 1);
            vf += __shfl_xor_sync(0xffffffffu, vf, 2);
            if ((l & 3) == 0) fout[(size_t)row * 128 + i] = vf + bfi;
        }
    }
}

// ---------------- launch ----------------
extern "C" void kernel_launch(void* const* d_in, const int* in_sizes, int n_in,
                              void* d_out, int out_size) {
    (void)in_sizes; (void)n_in; (void)out_size;
    const float* x  = (const float*)d_in[0];
    const float* fw = (const float*)d_in[1];
    const float* gw = (const float*)d_in[2];
    const float* Wf = (const float*)d_in[3];
    const float* bf = (const float*)d_in[4];
    const float* Wg = (const float*)d_in[5];
    const float* bg = (const float*)d_in[6];
    float* out  = (float*)d_out;
    float* fout = out;                      // [B,N]
    float* gout = out + (size_t)B_ * N_;    // [B,N,D]

    static bool attr_set = false;
    if (!attr_set) {
        cudaFuncSetAttribute(sde_main, cudaFuncAttributeMaxDynamicSharedMemorySize, SM_TOT);
        attr_set = true;
    }

    prep_x<<<256, 256>>>(x);
    sde_main<<<dim3(8, N_), 256, SM_TOT>>>(fw, gw, Wf, bf, Wg, bg, fout, gout);
}